// round 14
// baseline (speedup 1.0000x reference)
#include <cuda_runtime.h>
#include <cuda_bf16.h>
#include <cstdint>

#define N      4096
#define D      64
#define NB     256      // 2 persistent blocks per SM, all co-resident
#define NTHR   256      // 8 warps
#define ITERS  100
#define NT     32       // 32 row-slabs
#define NHT    64       // 64 column half-tiles (64 cols each)
#define SA     36       // A bf16 smem row stride (uint32)
#define SBF    36       // B fp32 smem row stride (floats); 144 B, 16B-aligned

// ---------------- device globals (no allocation allowed) --------------------------
__device__ float    g_K[(size_t)N * N];   // written only for flagged half-tiles
__device__ float    g_M[(size_t)N * N];
__device__ float    g_u[N], g_v[N];
__device__ unsigned g_bar_count;
__device__ unsigned g_bar_phase;          // monotone across replays; compared relatively
__device__ int      g_changed[ITERS];
__device__ float    g_cost;
__device__ int      g_map2[NT * NHT];     // per 128x64 half-tile flag
__device__ int      g_blockany[NB];

// ---------------- cp.async helpers -------------------------------------------------
__device__ __forceinline__ void cpa16(uint32_t dst, const void* src) {
    asm volatile("cp.async.cg.shared.global [%0], [%1], 16;" :: "r"(dst), "l"(src));
}
#define CP_COMMIT() asm volatile("cp.async.commit_group;")
#define CP_WAIT0()  asm volatile("cp.async.wait_group 0;")

// ---------------- grid barrier: arrivals atomic, polls are acquire LOADS -----------
__device__ __forceinline__ void gsync() {
    __syncthreads();
    if (threadIdx.x == 0) {
        __threadfence();
        unsigned ph = atomicAdd(&g_bar_phase, 0u);   // strong read BEFORE arrival
        if (atomicAdd(&g_bar_count, 1u) == (unsigned)NB - 1u) {
            atomicExch(&g_bar_count, 0u);
            atomicAdd(&g_bar_phase, 1u);             // release
        } else {
            unsigned cur;
            do {
                __nanosleep(64);
                asm volatile("ld.acquire.gpu.global.u32 %0, [%1];"
                             : "=r"(cur) : "l"(&g_bar_phase));
            } while (cur == ph);
        }
        __threadfence();
    }
    __syncthreads();
}

// =============== the whole pipeline in ONE persistent kernel =======================
__global__ void __launch_bounds__(NTHR, 2) kern_all(const float* __restrict__ x0,
                                                    const float* __restrict__ x1,
                                                    float* __restrict__ out) {
    // u32 pool: Ah[4608] | Bf 2x2304 | sqA32[128] | sqA64[128] | flags[64] = 37.3KB
    __shared__ uint32_t s_pool[9536];
    uint32_t* const Ah   = s_pool;
    float*    const Bf0  = (float*)(s_pool + 4608);        // 2 buffers x 2304
    float*    const sqA32 = (float*)(s_pool + 9216);
    float*    const sqA64 = (float*)(s_pool + 9344);
    int*      const flags = (int*)(s_pool + 9472);         // [tile][warp] 8x8
    float*    const sred  = (float*)s_pool;                // phase-2 overlay

    const int tid  = threadIdx.x;
    const int bid  = blockIdx.x;
    const int lane = tid & 31;
    const int w    = tid >> 5;                // 0..7
    const int gid  = lane >> 2;
    const int pid  = lane & 3;
    const int wm   = w >> 1;                  // 0..3 (32-row strips)
    const int wn2  = w & 1;                   // 0..1 (32-col strips in 64)

    if (bid == 0) {
        if (tid == 0) g_cost = 0.0f;
        if (tid < ITERS) g_changed[tid] = 0;
    }

    // =========== phase 1: per-block local conversion + screened GEMM ==============
    const int rs  = bid >> 3;                 // row slab 0..31
    const int cg8 = bid & 7;                  // column group: cols cg8*512..+512
    const uint32_t sb = (uint32_t)__cvta_generic_to_shared(s_pool);
    const uint32_t BfByte = 4608u * 4u;

    // B half-tile loader: 64 rows x 128B of fp32 dims 0..31 (8KB); 512 chunks
    auto loadB = [&](int buf, int h) {
#pragma unroll
        for (int j = 0; j < 2; j++) {
            int f = tid + j * NTHR;           // 0..511
            int r = f >> 3; int c4 = f & 7;
            int row = cg8 * 512 + h * 64 + r;
            cpa16(sb + BfByte + (uint32_t)buf * 9216u
                     + (uint32_t)(r * SBF + c4 * 4) * 4u,
                  x1 + (size_t)row * D + c4 * 4);
        }
    };
    loadB(0, 0);
    CP_COMMIT();

    // A slab: fp32 -> bf16 smem + in-pass row norms (overlaps the B cp.async)
    {
        const float* GA = x0 + (size_t)(rs * 128) * D;
#pragma unroll
        for (int i = 0; i < 8; i++) {
            int f = tid + i * NTHR;           // 0..2047
            int r = f >> 4; int q = f & 15;
            float4 v = *(const float4*)(GA + (size_t)r * D + q * 4);
            __nv_bfloat162 p0 = __floats2bfloat162_rn(v.x, v.y);
            __nv_bfloat162 p1 = __floats2bfloat162_rn(v.z, v.w);
            Ah[r * SA + q * 2]     = *(uint32_t*)&p0;
            Ah[r * SA + q * 2 + 1] = *(uint32_t*)&p1;
            float s = v.x * v.x + v.y * v.y + v.z * v.z + v.w * v.w;
            float s32 = (q < 8) ? s : 0.0f;
#pragma unroll
            for (int o = 1; o < 16; o <<= 1) {
                s   += __shfl_xor_sync(0xffffffffu, s,   o);
                s32 += __shfl_xor_sync(0xffffffffu, s32, o);
            }
            if ((lane & 15) == 0) { sqA32[r] = s32; sqA64[r] = s; }
        }
    }
    CP_WAIT0();
    __syncthreads();          // Ah + sq + first B visible

    const int gr = rs * 128 + wm * 32;
    float r032[2][2];
#pragma unroll
    for (int mi = 0; mi < 2; mi++) {
        r032[mi][0] = sqA32[wm * 32 + mi * 16 + gid];
        r032[mi][1] = sqA32[wm * 32 + mi * 16 + gid + 8];
    }

    const int AR = wm * 32, BR = wn2 * 32;
    int cur = 0;
    for (int h = 0; h < 8; h++) {
        if (h > 0) { CP_WAIT0(); __syncthreads(); }
        if (h < 7) { loadB(cur ^ 1, h + 1); CP_COMMIT(); }

        const float* Bf = Bf0 + cur * 2304;

        // per-lane sq1 over dims 0..31 for col BR+lane (conflict-free: stride 36)
        float s1 = 0.0f;
        {
            const float* brow = Bf + (BR + lane) * SBF;
#pragma unroll
            for (int j = 0; j < 8; j++) {
                float4 t = *(const float4*)(brow + j * 4);
                s1 += t.x * t.x + t.y * t.y + t.z * t.z + t.w * t.w;
            }
        }

        float acc[2][4][4];
#pragma unroll
        for (int mi = 0; mi < 2; mi++)
#pragma unroll
            for (int ni = 0; ni < 4; ni++)
#pragma unroll
                for (int f = 0; f < 4; f++) acc[mi][ni][f] = 0.0f;

        // mma dims 0..31: a from bf16 smem, b cvt-from-fp32 smem
#pragma unroll
        for (int kk = 0; kk < 2; kk++) {
            const int ac = kk * 8 + pid;
            uint32_t a[2][4], b[4][2];
#pragma unroll
            for (int mi = 0; mi < 2; mi++) {
                int r = AR + mi * 16 + gid;
                a[mi][0] = Ah[r * SA + ac];
                a[mi][1] = Ah[(r + 8) * SA + ac];
                a[mi][2] = Ah[r * SA + ac + 4];
                a[mi][3] = Ah[(r + 8) * SA + ac + 4];
            }
#pragma unroll
            for (int ni = 0; ni < 4; ni++) {
                const float* bc = Bf + (BR + ni * 8 + gid) * SBF;
                float2 f0 = *(const float2*)(bc + (kk * 8 + pid) * 2);
                float2 f1 = *(const float2*)(bc + (kk * 8 + pid + 4) * 2);
                asm("cvt.rn.bf16x2.f32 %0, %1, %2;" : "=r"(b[ni][0]) : "f"(f0.y), "f"(f0.x));
                asm("cvt.rn.bf16x2.f32 %0, %1, %2;" : "=r"(b[ni][1]) : "f"(f1.y), "f"(f1.x));
            }
#pragma unroll
            for (int mi = 0; mi < 2; mi++)
#pragma unroll
                for (int ni = 0; ni < 4; ni++)
                    asm volatile(
                        "mma.sync.aligned.m16n8k16.row.col.f32.bf16.bf16.f32 "
                        "{%0,%1,%2,%3}, {%4,%5,%6,%7}, {%8,%9}, {%0,%1,%2,%3};"
                        : "+f"(acc[mi][ni][0]), "+f"(acc[mi][ni][1]),
                          "+f"(acc[mi][ni][2]), "+f"(acc[mi][ni][3])
                        : "r"(a[mi][0]), "r"(a[mi][1]), "r"(a[mi][2]), "r"(a[mi][3]),
                          "r"(b[ni][0]), "r"(b[ni][1]));
        }

        // exact screen: partial M (dims 0..31) lower-bounds full M
        int need = 0;
#pragma unroll
        for (int ni = 0; ni < 4; ni++) {
            float s1a = __shfl_sync(0xffffffffu, s1, ni * 8 + 2 * pid);
            float s1b = __shfl_sync(0xffffffffu, s1, ni * 8 + 2 * pid + 1);
#pragma unroll
            for (int mi = 0; mi < 2; mi++) {
                float m0 = fmaf(-2.0f, acc[mi][ni][0], r032[mi][0] + s1a);
                float m1 = fmaf(-2.0f, acc[mi][ni][1], r032[mi][0] + s1b);
                float m2 = fmaf(-2.0f, acc[mi][ni][2], r032[mi][1] + s1a);
                float m3 = fmaf(-2.0f, acc[mi][ni][3], r032[mi][1] + s1b);
                need |= (fminf(fminf(m0, m1), fminf(m2, m3)) < 11.0f) ? 1 : 0;
            }
        }
        int anyb = __ballot_sync(0xffffffffu, need) ? 1 : 0;
        if (lane == 0) flags[h * 8 + w] = anyb;
        cur ^= 1;
    }
    __syncthreads();           // all flags visible

    // -------- cold pass: complete flagged half-tiles exactly (rare) --------------
    {
        int blkany = 0;
        for (int h = 0; h < 8; h++) {
            int f = flags[h * 8 + 0] | flags[h * 8 + 1] | flags[h * 8 + 2] |
                    flags[h * 8 + 3] | flags[h * 8 + 4] | flags[h * 8 + 5] |
                    flags[h * 8 + 6] | flags[h * 8 + 7];
            if (tid == 0) g_map2[rs * NHT + cg8 * 8 + h] = f;
            blkany |= f;
            if (!f) continue;

            const int gc = cg8 * 512 + h * 64 + wn2 * 32;
            // per-lane full sq1_64 for col gc+lane (from global fp32)
            float s1f = 0.0f;
            {
                const float* xr = x1 + (size_t)(gc + lane) * D;
#pragma unroll
                for (int j = 0; j < 16; j++) {
                    float4 t = *(const float4*)(xr + j * 4);
                    s1f += t.x * t.x + t.y * t.y + t.z * t.z + t.w * t.w;
                }
            }
            float acc[2][4][4];
#pragma unroll
            for (int mi = 0; mi < 2; mi++)
#pragma unroll
                for (int ni = 0; ni < 4; ni++)
#pragma unroll
                    for (int ff = 0; ff < 4; ff++) acc[mi][ni][ff] = 0.0f;
            // full 64-dim mma: a from bf16 smem, b cvt from global fp32
#pragma unroll
            for (int ks = 0; ks < 4; ks++) {
                const int ac = ks * 8 + pid;
                uint32_t a[2][4], b[4][2];
#pragma unroll
                for (int mi = 0; mi < 2; mi++) {
                    int r = AR + mi * 16 + gid;
                    a[mi][0] = Ah[r * SA + ac];
                    a[mi][1] = Ah[(r + 8) * SA + ac];
                    a[mi][2] = Ah[r * SA + ac + 4];
                    a[mi][3] = Ah[(r + 8) * SA + ac + 4];
                }
#pragma unroll
                for (int ni = 0; ni < 4; ni++) {
                    const float* xc = x1 + (size_t)(gc + ni * 8 + gid) * D + ks * 16;
                    float2 f0 = *(const float2*)(xc + 2 * pid);
                    float2 f1 = *(const float2*)(xc + 2 * pid + 8);
                    asm("cvt.rn.bf16x2.f32 %0, %1, %2;" : "=r"(b[ni][0]) : "f"(f0.y), "f"(f0.x));
                    asm("cvt.rn.bf16x2.f32 %0, %1, %2;" : "=r"(b[ni][1]) : "f"(f1.y), "f"(f1.x));
                }
#pragma unroll
                for (int mi = 0; mi < 2; mi++)
#pragma unroll
                    for (int ni = 0; ni < 4; ni++)
                        asm volatile(
                            "mma.sync.aligned.m16n8k16.row.col.f32.bf16.bf16.f32 "
                            "{%0,%1,%2,%3}, {%4,%5,%6,%7}, {%8,%9}, {%0,%1,%2,%3};"
                            : "+f"(acc[mi][ni][0]), "+f"(acc[mi][ni][1]),
                              "+f"(acc[mi][ni][2]), "+f"(acc[mi][ni][3])
                            : "r"(a[mi][0]), "r"(a[mi][1]), "r"(a[mi][2]), "r"(a[mi][3]),
                              "r"(b[ni][0]), "r"(b[ni][1]));
            }
#pragma unroll
            for (int mi = 0; mi < 2; mi++) {
                float s0a = sqA64[wm * 32 + mi * 16 + gid];
                float s0b = sqA64[wm * 32 + mi * 16 + gid + 8];
#pragma unroll
                for (int ni = 0; ni < 4; ni++) {
                    float s1a = __shfl_sync(0xffffffffu, s1f, ni * 8 + 2 * pid);
                    float s1b = __shfl_sync(0xffffffffu, s1f, ni * 8 + 2 * pid + 1);
                    int c = gc + ni * 8 + 2 * pid;
                    float m0 = fmaxf(fmaf(-2.0f, acc[mi][ni][0], s0a + s1a), 0.0f);
                    float m1 = fmaxf(fmaf(-2.0f, acc[mi][ni][1], s0a + s1b), 0.0f);
                    float m2 = fmaxf(fmaf(-2.0f, acc[mi][ni][2], s0b + s1a), 0.0f);
                    float m3 = fmaxf(fmaf(-2.0f, acc[mi][ni][3], s0b + s1b), 0.0f);
                    int r0 = gr + mi * 16 + gid;
                    *(float2*)(g_M + (size_t)r0 * N + c)       = make_float2(m0, m1);
                    *(float2*)(g_M + (size_t)(r0 + 8) * N + c) = make_float2(m2, m3);
                    *(float2*)(g_K + (size_t)r0 * N + c)       =
                        make_float2(expf(-10.0f * m0), expf(-10.0f * m1));
                    *(float2*)(g_K + (size_t)(r0 + 8) * N + c) =
                        make_float2(expf(-10.0f * m2), expf(-10.0f * m3));
                }
            }
        }
        if (tid == 0) g_blockany[bid] = blkany;
    }
    gsync();                   // the ONLY grid barrier on the zero fast path

    // =========== phase 2: Sinkhorn (or exact zero fast path) ======================
    {
        int loc = g_blockany[tid];            // NTHR == NB
        if (!__syncthreads_or(loc)) {
            if (bid == 0 && tid == 0) out[0] = 0.0f;   // P == 0 exactly
            return;                                     // uniform across blocks
        }
    }

    const float AB    = 1.0f / (float)N;
    const float DELTA = 1e-8f;
    {
        int gi = bid * NTHR + tid;
        if (gi < N) { g_u[gi] = 1.0f; g_v[gi] = 1.0f; }
    }
    gsync();

    for (int it = 0; it < ITERS; it++) {
        // u-pass: 16 rows/block, 2 rows/warp; skip all-zero half-tiles
#pragma unroll
        for (int rr = 0; rr < 2; rr++) {
            int r  = bid * 16 + w * 2 + rr;
            int rt = r >> 7;
            const int* map = g_map2 + rt * NHT;
            const float4* kr = (const float4*)(g_K + (size_t)r * N);
            const float4* vv = (const float4*)g_v;
            float s = 0.0f;
            for (int hct = 0; hct < NHT; hct++) {
                if (!map[hct]) continue;
                if (lane < 16) {
                    int j = hct * 16 + lane;
                    float4 kq = kr[j];
                    float4 vq = vv[j];
                    s += kq.x * vq.x + kq.y * vq.y + kq.z * vq.z + kq.w * vq.w;
                }
            }
#pragma unroll
            for (int o = 16; o; o >>= 1) s += __shfl_xor_sync(0xffffffffu, s, o);
            if (lane == 0) {
                float un = AB / (s + DELTA);
                if (un != g_u[r]) g_changed[it] = 1;
                g_u[r] = un;
            }
        }
        gsync();

        // v-pass: 16 cols/block; col = bid*16 + (tid>>4), 16-row stride
        {
            int cl  = tid >> 4;
            int ri  = tid & 15;
            int c   = bid * 16 + cl;
            int hct = bid >> 2;
            float s = 0.0f;
            for (int rt = 0; rt < NT; rt++) {
                if (!g_map2[rt * NHT + hct]) continue;
                int rbase = rt * 128;
#pragma unroll 8
                for (int r = rbase + ri; r < rbase + 128; r += 16)
                    s += g_K[(size_t)r * N + c] * g_u[r];
            }
            sred[tid] = s;
            __syncthreads();
            if (tid < 16) {
                float t = 0.0f;
#pragma unroll
                for (int g = 0; g < 16; g++) t += sred[tid * 16 + g];
                float vn = AB / (t + DELTA);
                int c2 = bid * 16 + tid;
                if (vn != g_v[c2]) g_changed[it] = 1;
                g_v[c2] = vn;
            }
        }
        gsync();

        if (g_changed[it] == 0) break;        // exact bitwise fixed point
    }

    // cost = sum_ij u_i * K_ij * v_j * M_ij (zero half-tiles contribute 0)
    {
        float wsum = 0.0f;
#pragma unroll
        for (int rr = 0; rr < 2; rr++) {
            int r  = bid * 16 + w * 2 + rr;
            int rt = r >> 7;
            const int* map = g_map2 + rt * NHT;
            const float4* kr = (const float4*)(g_K + (size_t)r * N);
            const float4* mr = (const float4*)(g_M + (size_t)r * N);
            const float4* vv = (const float4*)g_v;
            float s = 0.0f;
            for (int hct = 0; hct < NHT; hct++) {
                if (!map[hct]) continue;
                if (lane < 16) {
                    int j = hct * 16 + lane;
                    float4 kq = kr[j];
                    float4 mq = mr[j];
                    float4 vq = vv[j];
                    s += kq.x * mq.x * vq.x + kq.y * mq.y * vq.y
                       + kq.z * mq.z * vq.z + kq.w * mq.w * vq.w;
                }
            }
#pragma unroll
            for (int o = 16; o; o >>= 1) s += __shfl_xor_sync(0xffffffffu, s, o);
            if (lane == 0) wsum += s * g_u[r];
        }
        if (lane == 0) atomicAdd(&g_cost, wsum);
    }
    gsync();
    if (bid == 0 && tid == 0) out[0] = g_cost;
}

// ---------------- launch: ONE kernel ----------------------------------------------
extern "C" void kernel_launch(void* const* d_in, const int* in_sizes, int n_in,
                              void* d_out, int out_size) {
    const float* x0 = (const float*)d_in[0];
    const float* x1 = (const float*)d_in[1];
    float* out = (float*)d_out;
    kern_all<<<NB, NTHR>>>(x0, x1, out);
}

// round 15
// speedup vs baseline: 1.2443x; 1.2443x over previous
#include <cuda_runtime.h>
#include <cuda_bf16.h>
#include <cstdint>

#define N      4096
#define D      64
#define NB     256      // 2 persistent blocks per SM, all co-resident
#define NTHR   256      // 8 warps
#define ITERS  100
#define NT     32       // 32 row-slabs
#define NHT    64       // 64 column half-tiles (64 cols each)
#define SA     36       // A bf16 smem row stride (uint32)
#define SBH    20       // B bf16 half-tile row stride (uint32)

// ---------------- device globals (no allocation allowed) --------------------------
__device__ float    g_K[(size_t)N * N];   // written only for flagged half-tiles
__device__ float    g_M[(size_t)N * N];
__device__ float    g_u[N], g_v[N];
__device__ unsigned g_bar_count;
__device__ unsigned g_bar_phase;          // monotone across replays; compared relatively
__device__ int      g_changed[ITERS];
__device__ float    g_cost;
__device__ int      g_map2[NT * NHT];     // per 128x64 half-tile flag
__device__ int      g_blockany[NB];

// ---------------- grid barrier: arrivals atomic, polls are acquire LOADS -----------
__device__ __forceinline__ void gsync() {
    __syncthreads();
    if (threadIdx.x == 0) {
        __threadfence();
        unsigned ph = atomicAdd(&g_bar_phase, 0u);   // strong read BEFORE arrival
        if (atomicAdd(&g_bar_count, 1u) == (unsigned)NB - 1u) {
            atomicExch(&g_bar_count, 0u);
            atomicAdd(&g_bar_phase, 1u);             // release
        } else {
            unsigned cur;
            do {
                __nanosleep(64);
                asm volatile("ld.acquire.gpu.global.u32 %0, [%1];"
                             : "=r"(cur) : "l"(&g_bar_phase));
            } while (cur == ph);
        }
        __threadfence();
    }
    __syncthreads();
}

// ---------------- mma, dims 0..31, bf16 smem both sides; warp = 32x32 --------------
__device__ __forceinline__ void mma_lo_s(float (&acc)[2][4][4],
                                         const uint32_t* Ah, const uint32_t* Bh,
                                         int AR, int BR, int gid, int pid) {
#pragma unroll
    for (int kk = 0; kk < 2; kk++) {
        const int ac = kk * 8 + pid;
        const int bc = kk * 8 + pid;
        uint32_t a[2][4], b[4][2];
#pragma unroll
        for (int mi = 0; mi < 2; mi++) {
            int r = AR + mi * 16 + gid;
            a[mi][0] = Ah[r * SA + ac];
            a[mi][1] = Ah[(r + 8) * SA + ac];
            a[mi][2] = Ah[r * SA + ac + 4];
            a[mi][3] = Ah[(r + 8) * SA + ac + 4];
        }
#pragma unroll
        for (int ni = 0; ni < 4; ni++) {
            int c = BR + ni * 8 + gid;
            b[ni][0] = Bh[c * SBH + bc];
            b[ni][1] = Bh[c * SBH + bc + 4];
        }
#pragma unroll
        for (int mi = 0; mi < 2; mi++)
#pragma unroll
            for (int ni = 0; ni < 4; ni++)
                asm volatile(
                    "mma.sync.aligned.m16n8k16.row.col.f32.bf16.bf16.f32 "
                    "{%0,%1,%2,%3}, {%4,%5,%6,%7}, {%8,%9}, {%0,%1,%2,%3};"
                    : "+f"(acc[mi][ni][0]), "+f"(acc[mi][ni][1]),
                      "+f"(acc[mi][ni][2]), "+f"(acc[mi][ni][3])
                    : "r"(a[mi][0]), "r"(a[mi][1]), "r"(a[mi][2]), "r"(a[mi][3]),
                      "r"(b[ni][0]), "r"(b[ni][1]));
    }
}

// =============== the whole pipeline in ONE persistent kernel =======================
__global__ void __launch_bounds__(NTHR, 2) kern_all(const float* __restrict__ x0,
                                                    const float* __restrict__ x1,
                                                    float* __restrict__ out) {
    // u32 pool: Ah[4608] | Bb 2x1280 | sq1t 2x64 | sqA32[128] | sqA64[128] | flags[64]
    __shared__ uint32_t s_pool[7616];                // 30.5 KB
    uint32_t* const Ah    = s_pool;
    uint32_t* const Bb    = s_pool + 4608;           // 2 buffers x 1280
    float*    const sq1t  = (float*)(s_pool + 7168); // 2 x 64 (per-tile sq1, dims 0..31)
    float*    const sqA32 = (float*)(s_pool + 7296);
    float*    const sqA64 = (float*)(s_pool + 7424);
    int*      const flags = (int*)(s_pool + 7552);   // [tile][warp] 8x8
    float*    const sred  = (float*)s_pool;          // phase-2 overlay

    const int tid  = threadIdx.x;
    const int bid  = blockIdx.x;
    const int lane = tid & 31;
    const int w    = tid >> 5;                // 0..7
    const int gid  = lane >> 2;
    const int pid  = lane & 3;
    const int wm   = w >> 1;                  // 0..3 (32-row strips)
    const int wn2  = w & 1;                   // 0..1 (32-col strips in 64)

    if (bid == 0) {
        if (tid == 0) g_cost = 0.0f;
        if (tid < ITERS) g_changed[tid] = 0;
    }

    // =========== phase 1: local A conversion + reg-pipelined screened GEMM ========
    const int rs  = bid >> 3;                 // row slab 0..31
    const int cg8 = bid & 7;                  // column group: cols cg8*512..+512

    // -- B half-tile stage: LDG fp32 (dims 0..31) into regs --
    const int br1 = tid >> 3;                 // 0..31 (row within half of tile)
    const int bc4 = tid & 7;                  // float4 within 128B lo-half
    float4 breg[2];
    auto ldB = [&](int h) {
        const float* base = x1 + (size_t)(cg8 * 512 + h * 64) * D + bc4 * 4;
        breg[0] = *(const float4*)(base + (size_t)br1 * D);
        breg[1] = *(const float4*)(base + (size_t)(br1 + 32) * D);
    };
    // -- convert staged tile to bf16 smem + per-row sq1 (8-lane shfl tree) --
    auto stB = [&](int buf) {
        float sq0 = 0.0f, sq1v = 0.0f;
#pragma unroll
        for (int j = 0; j < 2; j++) {
            float4 v = breg[j];
            __nv_bfloat162 p0 = __floats2bfloat162_rn(v.x, v.y);
            __nv_bfloat162 p1 = __floats2bfloat162_rn(v.z, v.w);
            uint32_t* d = Bb + buf * 1280 + (br1 + j * 32) * SBH + bc4 * 2;
            d[0] = *(uint32_t*)&p0;
            d[1] = *(uint32_t*)&p1;
            float s = v.x * v.x + v.y * v.y + v.z * v.z + v.w * v.w;
            if (j == 0) sq0 = s; else sq1v = s;
        }
#pragma unroll
        for (int o = 1; o < 8; o <<= 1) {
            sq0  += __shfl_xor_sync(0xffffffffu, sq0,  o);
            sq1v += __shfl_xor_sync(0xffffffffu, sq1v, o);
        }
        if ((lane & 7) == 0) {
            sq1t[buf * 64 + br1]      = sq0;
            sq1t[buf * 64 + br1 + 32] = sq1v;
        }
    };

    ldB(0);                                   // tile-0 LDG in flight

    // -- A slab: fp32 -> bf16 smem + in-pass row norms --
    {
        const float* GA = x0 + (size_t)(rs * 128) * D;
#pragma unroll
        for (int i = 0; i < 8; i++) {
            int f = tid + i * NTHR;           // 0..2047
            int r = f >> 4; int q = f & 15;
            float4 v = *(const float4*)(GA + (size_t)r * D + q * 4);
            __nv_bfloat162 p0 = __floats2bfloat162_rn(v.x, v.y);
            __nv_bfloat162 p1 = __floats2bfloat162_rn(v.z, v.w);
            Ah[r * SA + q * 2]     = *(uint32_t*)&p0;
            Ah[r * SA + q * 2 + 1] = *(uint32_t*)&p1;
            float s = v.x * v.x + v.y * v.y + v.z * v.z + v.w * v.w;
            float s32 = (q < 8) ? s : 0.0f;
#pragma unroll
            for (int o = 1; o < 16; o <<= 1) {
                s   += __shfl_xor_sync(0xffffffffu, s,   o);
                s32 += __shfl_xor_sync(0xffffffffu, s32, o);
            }
            if ((lane & 15) == 0) { sqA32[r] = s32; sqA64[r] = s; }
        }
    }

    const int gr = rs * 128 + wm * 32;
    const int AR = wm * 32, BR = wn2 * 32;
    float r032[2][2];
    int cur = 0;
    for (int h = 0; h < 8; h++) {
        stB(cur);
        __syncthreads();       // buf cur + (h==0: Ah/sq) visible to all warps
        if (h == 0) {
#pragma unroll
            for (int mi = 0; mi < 2; mi++) {
                r032[mi][0] = sqA32[wm * 32 + mi * 16 + gid];
                r032[mi][1] = sqA32[wm * 32 + mi * 16 + gid + 8];
            }
        }
        if (h < 7) ldB(h + 1); // LDG latency hides under mma + screen

        float acc[2][4][4];
#pragma unroll
        for (int mi = 0; mi < 2; mi++)
#pragma unroll
            for (int ni = 0; ni < 4; ni++)
#pragma unroll
                for (int f = 0; f < 4; f++) acc[mi][ni][f] = 0.0f;

        mma_lo_s(acc, Ah, Bb + cur * 1280, AR, BR, gid, pid);   // dims 0..31

        // exact screen: partial M (dims 0..31) lower-bounds full M
        int need = 0;
#pragma unroll
        for (int ni = 0; ni < 4; ni++) {
            int lc = wn2 * 32 + ni * 8 + 2 * pid;
            float s1a = sq1t[cur * 64 + lc];
            float s1b = sq1t[cur * 64 + lc + 1];
#pragma unroll
            for (int mi = 0; mi < 2; mi++) {
                float m0 = fmaf(-2.0f, acc[mi][ni][0], r032[mi][0] + s1a);
                float m1 = fmaf(-2.0f, acc[mi][ni][1], r032[mi][0] + s1b);
                float m2 = fmaf(-2.0f, acc[mi][ni][2], r032[mi][1] + s1a);
                float m3 = fmaf(-2.0f, acc[mi][ni][3], r032[mi][1] + s1b);
                need |= (fminf(fminf(m0, m1), fminf(m2, m3)) < 11.0f) ? 1 : 0;
            }
        }
        int anyb = __ballot_sync(0xffffffffu, need) ? 1 : 0;
        if (lane == 0) flags[h * 8 + w] = anyb;
        cur ^= 1;
    }
    __syncthreads();           // all flags visible

    // -------- cold pass: complete flagged half-tiles exactly (rare) --------------
    {
        int blkany = 0;
        for (int h = 0; h < 8; h++) {
            int f = flags[h * 8 + 0] | flags[h * 8 + 1] | flags[h * 8 + 2] |
                    flags[h * 8 + 3] | flags[h * 8 + 4] | flags[h * 8 + 5] |
                    flags[h * 8 + 6] | flags[h * 8 + 7];
            if (tid == 0) g_map2[rs * NHT + cg8 * 8 + h] = f;
            blkany |= f;
            if (!f) continue;

            const int gc = cg8 * 512 + h * 64 + wn2 * 32;
            // per-lane full sq1_64 for col gc+lane (from global fp32)
            float s1f = 0.0f;
            {
                const float* xr = x1 + (size_t)(gc + lane) * D;
#pragma unroll
                for (int j = 0; j < 16; j++) {
                    float4 t = *(const float4*)(xr + j * 4);
                    s1f += t.x * t.x + t.y * t.y + t.z * t.z + t.w * t.w;
                }
            }
            float acc[2][4][4];
#pragma unroll
            for (int mi = 0; mi < 2; mi++)
#pragma unroll
                for (int ni = 0; ni < 4; ni++)
#pragma unroll
                    for (int ff = 0; ff < 4; ff++) acc[mi][ni][ff] = 0.0f;
            // full 64-dim mma: a from bf16 smem, b cvt from global fp32
#pragma unroll
            for (int ks = 0; ks < 4; ks++) {
                const int ac = ks * 8 + pid;
                uint32_t a[2][4], b[4][2];
#pragma unroll
                for (int mi = 0; mi < 2; mi++) {
                    int r = AR + mi * 16 + gid;
                    a[mi][0] = Ah[r * SA + ac];
                    a[mi][1] = Ah[(r + 8) * SA + ac];
                    a[mi][2] = Ah[r * SA + ac + 4];
                    a[mi][3] = Ah[(r + 8) * SA + ac + 4];
                }
#pragma unroll
                for (int ni = 0; ni < 4; ni++) {
                    const float* xc = x1 + (size_t)(gc + ni * 8 + gid) * D + ks * 16;
                    float2 f0 = *(const float2*)(xc + 2 * pid);
                    float2 f1 = *(const float2*)(xc + 2 * pid + 8);
                    asm("cvt.rn.bf16x2.f32 %0, %1, %2;" : "=r"(b[ni][0]) : "f"(f0.y), "f"(f0.x));
                    asm("cvt.rn.bf16x2.f32 %0, %1, %2;" : "=r"(b[ni][1]) : "f"(f1.y), "f"(f1.x));
                }
#pragma unroll
                for (int mi = 0; mi < 2; mi++)
#pragma unroll
                    for (int ni = 0; ni < 4; ni++)
                        asm volatile(
                            "mma.sync.aligned.m16n8k16.row.col.f32.bf16.bf16.f32 "
                            "{%0,%1,%2,%3}, {%4,%5,%6,%7}, {%8,%9}, {%0,%1,%2,%3};"
                            : "+f"(acc[mi][ni][0]), "+f"(acc[mi][ni][1]),
                              "+f"(acc[mi][ni][2]), "+f"(acc[mi][ni][3])
                            : "r"(a[mi][0]), "r"(a[mi][1]), "r"(a[mi][2]), "r"(a[mi][3]),
                              "r"(b[ni][0]), "r"(b[ni][1]));
            }
#pragma unroll
            for (int mi = 0; mi < 2; mi++) {
                float s0a = sqA64[wm * 32 + mi * 16 + gid];
                float s0b = sqA64[wm * 32 + mi * 16 + gid + 8];
#pragma unroll
                for (int ni = 0; ni < 4; ni++) {
                    float s1a = __shfl_sync(0xffffffffu, s1f, ni * 8 + 2 * pid);
                    float s1b = __shfl_sync(0xffffffffu, s1f, ni * 8 + 2 * pid + 1);
                    int c = gc + ni * 8 + 2 * pid;
                    float m0 = fmaxf(fmaf(-2.0f, acc[mi][ni][0], s0a + s1a), 0.0f);
                    float m1 = fmaxf(fmaf(-2.0f, acc[mi][ni][1], s0a + s1b), 0.0f);
                    float m2 = fmaxf(fmaf(-2.0f, acc[mi][ni][2], s0b + s1a), 0.0f);
                    float m3 = fmaxf(fmaf(-2.0f, acc[mi][ni][3], s0b + s1b), 0.0f);
                    int r0 = gr + mi * 16 + gid;
                    *(float2*)(g_M + (size_t)r0 * N + c)       = make_float2(m0, m1);
                    *(float2*)(g_M + (size_t)(r0 + 8) * N + c) = make_float2(m2, m3);
                    *(float2*)(g_K + (size_t)r0 * N + c)       =
                        make_float2(expf(-10.0f * m0), expf(-10.0f * m1));
                    *(float2*)(g_K + (size_t)(r0 + 8) * N + c) =
                        make_float2(expf(-10.0f * m2), expf(-10.0f * m3));
                }
            }
        }
        if (tid == 0) g_blockany[bid] = blkany;
    }
    gsync();                   // the ONLY grid barrier on the zero fast path

    // =========== phase 2: Sinkhorn (or exact zero fast path) ======================
    {
        int loc = g_blockany[tid];            // NTHR == NB
        if (!__syncthreads_or(loc)) {
            if (bid == 0 && tid == 0) out[0] = 0.0f;   // P == 0 exactly
            return;                                     // uniform across blocks
        }
    }

    const float AB    = 1.0f / (float)N;
    const float DELTA = 1e-8f;
    {
        int gi = bid * NTHR + tid;
        if (gi < N) { g_u[gi] = 1.0f; g_v[gi] = 1.0f; }
    }
    gsync();

    for (int it = 0; it < ITERS; it++) {
        // u-pass: 16 rows/block, 2 rows/warp; skip all-zero half-tiles
#pragma unroll
        for (int rr = 0; rr < 2; rr++) {
            int r  = bid * 16 + w * 2 + rr;
            int rt = r >> 7;
            const int* map = g_map2 + rt * NHT;
            const float4* kr = (const float4*)(g_K + (size_t)r * N);
            const float4* vv = (const float4*)g_v;
            float s = 0.0f;
            for (int hct = 0; hct < NHT; hct++) {
                if (!map[hct]) continue;
                if (lane < 16) {
                    int j = hct * 16 + lane;
                    float4 kq = kr[j];
                    float4 vq = vv[j];
                    s += kq.x * vq.x + kq.y * vq.y + kq.z * vq.z + kq.w * vq.w;
                }
            }
#pragma unroll
            for (int o = 16; o; o >>= 1) s += __shfl_xor_sync(0xffffffffu, s, o);
            if (lane == 0) {
                float un = AB / (s + DELTA);
                if (un != g_u[r]) g_changed[it] = 1;
                g_u[r] = un;
            }
        }
        gsync();

        // v-pass: 16 cols/block; col = bid*16 + (tid>>4), 16-row stride
        {
            int cl  = tid >> 4;
            int ri  = tid & 15;
            int c   = bid * 16 + cl;
            int hct = bid >> 2;
            float s = 0.0f;
            for (int rt = 0; rt < NT; rt++) {
                if (!g_map2[rt * NHT + hct]) continue;
                int rbase = rt * 128;
#pragma unroll 8
                for (int r = rbase + ri; r < rbase + 128; r += 16)
                    s += g_K[(size_t)r * N + c] * g_u[r];
            }
            sred[tid] = s;
            __syncthreads();
            if (tid < 16) {
                float t = 0.0f;
#pragma unroll
                for (int g = 0; g < 16; g++) t += sred[tid * 16 + g];
                float vn = AB / (t + DELTA);
                int c2 = bid * 16 + tid;
                if (vn != g_v[c2]) g_changed[it] = 1;
                g_v[c2] = vn;
            }
        }
        gsync();

        if (g_changed[it] == 0) break;        // exact bitwise fixed point
    }

    // cost = sum_ij u_i * K_ij * v_j * M_ij (zero half-tiles contribute 0)
    {
        float wsum = 0.0f;
#pragma unroll
        for (int rr = 0; rr < 2; rr++) {
            int r  = bid * 16 + w * 2 + rr;
            int rt = r >> 7;
            const int* map = g_map2 + rt * NHT;
            const float4* kr = (const float4*)(g_K + (size_t)r * N);
            const float4* mr = (const float4*)(g_M + (size_t)r * N);
            const float4* vv = (const float4*)g_v;
            float s = 0.0f;
            for (int hct = 0; hct < NHT; hct++) {
                if (!map[hct]) continue;
                if (lane < 16) {
                    int j = hct * 16 + lane;
                    float4 kq = kr[j];
                    float4 mq = mr[j];
                    float4 vq = vv[j];
                    s += kq.x * mq.x * vq.x + kq.y * mq.y * vq.y
                       + kq.z * mq.z * vq.z + kq.w * mq.w * vq.w;
                }
            }
#pragma unroll
            for (int o = 16; o; o >>= 1) s += __shfl_xor_sync(0xffffffffu, s, o);
            if (lane == 0) wsum += s * g_u[r];
        }
        if (lane == 0) atomicAdd(&g_cost, wsum);
    }
    gsync();
    if (bid == 0 && tid == 0) out[0] = g_cost;
}

// ---------------- launch: ONE kernel ----------------------------------------------
extern "C" void kernel_launch(void* const* d_in, const int* in_sizes, int n_in,
                              void* d_out, int out_size) {
    const float* x0 = (const float*)d_in[0];
    const float* x1 = (const float*)d_in[1];
    float* out = (float*)d_out;
    kern_all<<<NB, NTHR>>>(x0, x1, out);
}